// round 14
// baseline (speedup 1.0000x reference)
#include <cuda_runtime.h>
#include <cuda_bf16.h>
#include <math.h>
#include <stdint.h>

#define BB 32768
#define DD 1024
#define KK 512
#define INV_T 10.0f

// ---------------- scratch (static device globals) ----------------------------
__device__ __align__(16) __nv_bfloat16 g_Ss[16777216];   // scores_s bf16
__device__ __align__(16) __nv_bfloat16 g_E[16777216];    // E bf16
__device__ __align__(16) __nv_bfloat16 g_Zb[33554432];   // Z bf16 (s, then t)
__device__ __align__(16) __nv_bfloat16 g_W[524288];      // W_net bf16
__device__ __align__(16) __nv_bfloat16 g_Cn[262144];     // normalized protos bf16
__device__ float g_ss[2 * BB];      // row sumsq of Z (both branches)
__device__ float g_R[KK];
__device__ float g_alpha[KK];
__device__ float g_S;
__device__ float g_loss;

// ---------------- helpers ------------------------------------------------------
__device__ __forceinline__ uint32_t smem_u32(const void* p) {
    uint32_t a;
    asm("{ .reg .u64 t; cvta.to.shared.u64 t, %1; cvt.u32.u64 %0, t; }"
        : "=r"(a) : "l"(p));
    return a;
}
__device__ __forceinline__ void cp_async16(uint32_t saddr, const void* g) {
    asm volatile("cp.async.cg.shared.global [%0], [%1], 16;"
                 :: "r"(saddr), "l"(g) : "memory");
}
__device__ __forceinline__ void ldsm_x4(uint32_t* r, uint32_t addr) {
    asm volatile("ldmatrix.sync.aligned.m8n8.x4.shared.b16 {%0,%1,%2,%3}, [%4];"
                 : "=r"(r[0]), "=r"(r[1]), "=r"(r[2]), "=r"(r[3]) : "r"(addr));
}
__device__ __forceinline__ void mma16816(float* c, const uint32_t* a,
                                         uint32_t b0, uint32_t b1) {
    asm volatile(
        "mma.sync.aligned.m16n8k16.row.col.f32.bf16.bf16.f32 "
        "{%0,%1,%2,%3}, {%4,%5,%6,%7}, {%8,%9}, {%0,%1,%2,%3};"
        : "+f"(c[0]), "+f"(c[1]), "+f"(c[2]), "+f"(c[3])
        : "r"(a[0]), "r"(a[1]), "r"(a[2]), "r"(a[3]), "r"(b0), "r"(b1));
}
#define SWZ(o) ((o) ^ (((o) >> 3) & 0x70))

// fast e^x on the FMA pipe (exp2-based, degree-6 poly, rel err ~6e-8)
__device__ __forceinline__ float fexp(float x) {
    float y = x * 1.4426950408889634f;
    float t = y + 12582912.0f;
    int e = __float_as_int(t) - 0x4B400000;
    float f = y - (t - 12582912.0f);
    float p = 1.5403530e-4f;
    p = fmaf(p, f, 1.3333558e-3f);
    p = fmaf(p, f, 9.6181291e-3f);
    p = fmaf(p, f, 5.5504109e-2f);
    p = fmaf(p, f, 2.4022651e-1f);
    p = fmaf(p, f, 6.9314718e-1f);
    p = fmaf(p, f, 1.0f);
    return p * __int_as_float((e + 127) << 23);
}

__device__ __forceinline__ __nv_bfloat162 pack2(float a, float b) {
    return __halves2bfloat162(__float2bfloat16(a), __float2bfloat16(b));
}

// ---------------- init ----------------------------------------------------------
__global__ void k_init() {
    int i = blockIdx.x * blockDim.x + threadIdx.x;     // 65536 threads
    g_ss[i] = 0.0f;
    if (i < KK) g_R[i] = 0.0f;
    if (i == 0) g_loss = 0.0f;
}

// ---------------- Cn = l2norm rows of W_proto -> bf16 ---------------------------
__global__ void k_proto(const float* __restrict__ W) {
    int row = blockIdx.x;
    int t = threadIdx.x;
    float4 v = ((const float4*)(W + (size_t)row * KK))[t];
    float s = v.x * v.x + v.y * v.y + v.z * v.z + v.w * v.w;
    __shared__ float sm[128];
    sm[t] = s;
    __syncthreads();
    for (int o = 64; o > 0; o >>= 1) {
        if (t < o) sm[t] += sm[t + o];
        __syncthreads();
    }
    float inv = rsqrtf(sm[0]);
    __nv_bfloat162* hp = (__nv_bfloat162*)(g_Cn + (size_t)row * KK + t * 4);
    hp[0] = pack2(v.x * inv, v.y * inv);
    hp[1] = pack2(v.z * inv, v.w * inv);
}

// ---------------- f32 -> bf16 (W_net only; tiny) ----------------------------------
__global__ void k_conv(const float* __restrict__ x, __nv_bfloat16* __restrict__ hd,
                       int n4) {
    int i = blockIdx.x * blockDim.x + threadIdx.x;
    int stride = gridDim.x * blockDim.x;
    for (; i < n4; i += stride) {
        float4 v = ((const float4*)x)[i];
        __nv_bfloat162* hp = (__nv_bfloat162*)(hd + (size_t)i * 4);
        hp[0] = pack2(v.x, v.y);
        hp[1] = pack2(v.z, v.w);
    }
}

// ================= gemm1 batched (4 warps, 64x64 warp tiles) =====================
// Zb[0:B) = s@W^T, Zb[B:2B) = t@W^T, + row sumsq. Register f32->bf16 convert.
#define G1_ABF 0
#define G1_BT 32768
#define G1_SMEM 65536
__global__ void __launch_bounds__(128, 2)
k_gemm1f(const float* __restrict__ S, const float* __restrict__ T,
         const __nv_bfloat16* __restrict__ B, __nv_bfloat16* __restrict__ C) {
    extern __shared__ char smem[];
    const int Kd = DD;          // 1024
    const int NT = Kd >> 6;     // 16 k-tiles

    int tid = threadIdx.x, wid = tid >> 5, lane = tid & 31;
    int by = blockIdx.y;
    const float* A = (by < 256) ? S : T;
    int am0 = (by & 255) * 128;
    int m0 = by * 128;
    int n0 = blockIdx.x * 128;
    int wm = wid >> 1, wn = wid & 1;         // 2x2 warp grid, 64x64 tiles

    uint32_t s_base = smem_u32(smem);

    // --- B loader: 16KB tile, 1024 chunks / 128 threads = 8 each ---
    int lrow = tid >> 3, lseg = tid & 7;     // 16 rows x 8 segs per pass
    const __nv_bfloat16* gB0 = B + (size_t)(n0 + lrow) * Kd + lseg * 8;
    auto loadB = [&](int kt, int st) {
        uint32_t sa = s_base + G1_BT + (uint32_t)st * 16384;
        int kc = kt * 64;
#pragma unroll
        for (int p = 0; p < 8; p++) {
            uint32_t so = SWZ((lrow + p * 16) * 128 + lseg * 16);
            cp_async16(sa + so, gB0 + (size_t)p * 16 * Kd + kc);
        }
        asm volatile("cp.async.commit_group;" ::: "memory");
    };

    // --- A loader: quarter-granularity (16 f32 cols), 4 chunks/thread/quarter ---
    // chunk c = tid + 128*i : row = c>>2 (0..127), seg = c&3 (4 f32 = 16B)
    int arow = tid >> 2, aseg = tid & 3;
    const float* gA0 = A + (size_t)(am0 + arow) * Kd + aseg * 4;
    uint32_t sbase[4];
#pragma unroll
    for (int i = 0; i < 4; i++)
        sbase[i] = SWZ((uint32_t)((arow + i * 32) * 128 + aseg * 8));

    float4 fb[4];
    auto ldgA = [&](int kt, int q) {
#pragma unroll
        for (int i = 0; i < 4; i++)
            fb[i] = *(const float4*)(gA0 + (size_t)i * 32 * Kd + kt * 64 + q * 16);
    };
    auto stsA = [&](int st, int q) {
        uint32_t ab = s_base + G1_ABF + (uint32_t)st * 16384;
        uint32_t qx = (uint32_t)(q << 5);
#pragma unroll
        for (int i = 0; i < 4; i++) {
            __nv_bfloat162 q0 = pack2(fb[i].x, fb[i].y);
            __nv_bfloat162 q1 = pack2(fb[i].z, fb[i].w);
            asm volatile("st.shared.v2.b32 [%0], {%1,%2};"
                         :: "r"(ab + (sbase[i] ^ qx)),
                            "r"(*(uint32_t*)&q0), "r"(*(uint32_t*)&q1) : "memory");
        }
    };

    // --- ldmatrix offsets ---
    uint32_t offA[4], offB[4];
    {
        int rA = (lane & 7) + ((lane >> 3) & 1) * 8;
        int sA = (lane >> 4) * 16;
#pragma unroll
        for (int im = 0; im < 4; im++) {
            int row = wm * 64 + im * 16 + rA;
            offA[im] = (uint32_t)(row * 128) | (uint32_t)(sA ^ ((row & 7) << 4));
        }
        int rB = (lane & 7) + ((lane >> 4) & 1) * 8;
        int sB = ((lane >> 3) & 1) * 16;
#pragma unroll
        for (int j = 0; j < 4; j++) {
            int row = wn * 64 + j * 16 + rB;
            offB[j] = (uint32_t)(row * 128) | (uint32_t)(sB ^ ((row & 7) << 4));
        }
    }

    float acc[4][8][4];
#pragma unroll
    for (int i = 0; i < 4; i++)
#pragma unroll
        for (int j = 0; j < 8; j++)
#pragma unroll
            for (int k = 0; k < 4; k++) acc[i][j][k] = 0.0f;

    // --- prologue: tile 0 ---
    loadB(0, 0);
#pragma unroll
    for (int q = 0; q < 4; q++) { ldgA(0, q); stsA(0, q); }
    asm volatile("cp.async.wait_group 0;" ::: "memory");
    __syncthreads();

    for (int kt = 0; kt < NT; kt++) {
        int st = kt & 1;
        bool more = (kt + 1 < NT);
        if (more) {
            loadB(kt + 1, st ^ 1);
            ldgA(kt + 1, 0);
        }
        uint32_t sbA = s_base + G1_ABF + (uint32_t)st * 16384;
        uint32_t sbB = s_base + G1_BT + (uint32_t)st * 16384;
#pragma unroll
        for (int ks = 0; ks < 4; ks++) {
            uint32_t kx = (uint32_t)(ks << 5);
            uint32_t a[4][4], b[4][4];
#pragma unroll
            for (int im = 0; im < 4; im++) ldsm_x4(a[im], sbA + (offA[im] ^ kx));
#pragma unroll
            for (int j = 0; j < 4; j++) ldsm_x4(b[j], sbB + (offB[j] ^ kx));
#pragma unroll
            for (int im = 0; im < 4; im++)
#pragma unroll
                for (int j = 0; j < 4; j++) {
                    mma16816(acc[im][j * 2 + 0], a[im], b[j][0], b[j][1]);
                    mma16816(acc[im][j * 2 + 1], a[im], b[j][2], b[j][3]);
                }
            if (more) {
                stsA(st ^ 1, ks);                 // convert quarter ks
                if (ks < 3) ldgA(kt + 1, ks + 1); // prefetch next quarter
            }
        }
        if (more) asm volatile("cp.async.wait_group 0;" ::: "memory");
        __syncthreads();
    }

    // ---- epilogue: bf16 out + row sumsq ----
#pragma unroll
    for (int im = 0; im < 4; im++) {
        int m = m0 + wm * 64 + im * 16 + (lane >> 2);
        float s0 = 0.0f, s1 = 0.0f;
#pragma unroll
        for (int jn = 0; jn < 8; jn++) {
            int n = n0 + wn * 64 + jn * 8 + (lane & 3) * 2;
            float c0 = acc[im][jn][0], c1 = acc[im][jn][1];
            float c2 = acc[im][jn][2], c3 = acc[im][jn][3];
            s0 += c0 * c0 + c1 * c1;
            s1 += c2 * c2 + c3 * c3;
            *(__nv_bfloat162*)(C + (size_t)m * KK + n) = pack2(c0, c1);
            *(__nv_bfloat162*)(C + (size_t)(m + 8) * KK + n) = pack2(c2, c3);
        }
        s0 += __shfl_xor_sync(0xffffffffu, s0, 1);
        s0 += __shfl_xor_sync(0xffffffffu, s0, 2);
        s1 += __shfl_xor_sync(0xffffffffu, s1, 1);
        s1 += __shfl_xor_sync(0xffffffffu, s1, 2);
        if ((lane & 3) == 0) {
            atomicAdd(&g_ss[m], s0);
            atomicAdd(&g_ss[m + 8], s1);
        }
    }
}

// ================= gemm2 batched: scores (student) / E (teacher) =================
// invn computed inline from g_ss. (unchanged from R13)
#define STAGES 3
#define STAGE_BYTES 32768
__global__ void __launch_bounds__(256, 2)
k_gemm(const __nv_bfloat16* __restrict__ A, const __nv_bfloat16* __restrict__ B,
       __nv_bfloat16* __restrict__ Cs, __nv_bfloat16* __restrict__ Ce) {
    extern __shared__ char smem[];
    __shared__ float scp[2][128];

    int tid = threadIdx.x, wid = tid >> 5, lane = tid & 31;
    int by = blockIdx.y;
    int m0 = by * 128;
    int n0 = blockIdx.x * 128;
    int teacher = (by >= 256);
    __nv_bfloat16* C = teacher ? (Ce + (size_t)(m0 - BB) * KK)
                               : (Cs + (size_t)m0 * KK);
    int wm = wid >> 2, wn = wid & 3;

    uint32_t s_base = smem_u32(smem);
    const int NT = KK >> 6;                  // 8

    int lrow = tid >> 3, lseg = tid & 7;
    const __nv_bfloat16* gA0 = A + (size_t)(m0 + lrow) * KK + lseg * 8;
    const __nv_bfloat16* gB0 = B + (size_t)(n0 + lrow) * KK + lseg * 8;
    auto load = [&](int kt, int st) {
        int kc = kt * 64;
        uint32_t sa = s_base + st * STAGE_BYTES;
#pragma unroll
        for (int p = 0; p < 4; p++) {
            uint32_t so = SWZ((lrow + p * 32) * 128 + lseg * 16);
            cp_async16(sa + so, gA0 + (size_t)p * 32 * KK + kc);
            cp_async16(sa + 16384 + so, gB0 + (size_t)p * 32 * KK + kc);
        }
        asm volatile("cp.async.commit_group;" ::: "memory");
    };

    uint32_t offA[4], offB[2];
    {
        int rA = (lane & 7) + ((lane >> 3) & 1) * 8;
        int sA = (lane >> 4) * 16;
#pragma unroll
        for (int im = 0; im < 4; im++) {
            int row = wm * 64 + im * 16 + rA;
            offA[im] = (uint32_t)(row * 128) | (uint32_t)(sA ^ ((row & 7) << 4));
        }
        int rB = (lane & 7) + ((lane >> 4) & 1) * 8;
        int sB = ((lane >> 3) & 1) * 16;
#pragma unroll
        for (int j = 0; j < 2; j++) {
            int row = wn * 32 + j * 16 + rB;
            offB[j] = 16384u + ((uint32_t)(row * 128) |
                                (uint32_t)(sB ^ ((row & 7) << 4)));
        }
    }

    float acc[4][4][4];
#pragma unroll
    for (int i = 0; i < 4; i++)
#pragma unroll
        for (int j = 0; j < 4; j++)
#pragma unroll
            for (int k = 0; k < 4; k++) acc[i][j][k] = 0.0f;

    load(0, 0);
    load(1, 1);

    for (int kt = 0; kt < NT; kt++) {
        asm volatile("cp.async.wait_group 1;" ::: "memory");
        __syncthreads();
        uint32_t sb = s_base + (uint32_t)(kt % 3) * STAGE_BYTES;
#pragma unroll
        for (int ks = 0; ks < 4; ks++) {
            uint32_t kx = (uint32_t)(ks << 5);
            uint32_t a[4][4], b[2][4];
#pragma unroll
            for (int im = 0; im < 4; im++) ldsm_x4(a[im], sb + (offA[im] ^ kx));
#pragma unroll
            for (int j = 0; j < 2; j++) ldsm_x4(b[j], sb + (offB[j] ^ kx));
#pragma unroll
            for (int im = 0; im < 4; im++)
#pragma unroll
                for (int j = 0; j < 2; j++) {
                    mma16816(acc[im][j * 2 + 0], a[im], b[j][0], b[j][1]);
                    mma16816(acc[im][j * 2 + 1], a[im], b[j][2], b[j][3]);
                }
        }
        if (kt + 2 < NT) load(kt + 2, (kt + 2) % 3);
        else asm volatile("cp.async.commit_group;" ::: "memory");
    }

    float ce0[4] = {0, 0, 0, 0}, ce1[4] = {0, 0, 0, 0};
#pragma unroll
    for (int im = 0; im < 4; im++) {
        int m = m0 + wm * 64 + im * 16 + (lane >> 2);
        int ml = wm * 64 + im * 16 + (lane >> 2);
        float i0 = rsqrtf(g_ss[m]), i1 = rsqrtf(g_ss[m + 8]);
#pragma unroll
        for (int jn = 0; jn < 4; jn++) {
            int n = n0 + wn * 32 + jn * 8 + (lane & 3) * 2;
            float c0 = acc[im][jn][0] * i0, c1 = acc[im][jn][1] * i0;
            float c2 = acc[im][jn][2] * i1, c3 = acc[im][jn][3] * i1;
            if (teacher) {
                c0 = fexp((c0 - 1.0f) * INV_T);
                c1 = fexp((c1 - 1.0f) * INV_T);
                c2 = fexp((c2 - 1.0f) * INV_T);
                c3 = fexp((c3 - 1.0f) * INV_T);
                ce0[jn] += c0 + c2;
                ce1[jn] += c1 + c3;
            }
            *(__nv_bfloat162*)(C + (size_t)ml * KK + n) = pack2(c0, c1);
            *(__nv_bfloat162*)(C + (size_t)(ml + 8) * KK + n) = pack2(c2, c3);
        }
    }
    if (teacher) {
#pragma unroll
        for (int jn = 0; jn < 4; jn++) {
#pragma unroll
            for (int o = 4; o < 32; o <<= 1) {
                ce0[jn] += __shfl_xor_sync(0xffffffffu, ce0[jn], o);
                ce1[jn] += __shfl_xor_sync(0xffffffffu, ce1[jn], o);
            }
        }
        if (lane < 4) {
#pragma unroll
            for (int jn = 0; jn < 4; jn++) {
                scp[wm][wn * 32 + jn * 8 + lane * 2 + 0] = ce0[jn];
                scp[wm][wn * 32 + jn * 8 + lane * 2 + 1] = ce1[jn];
            }
        }
        __syncthreads();
        if (tid < 128)
            atomicAdd(&g_R[n0 + tid], scp[0][tid] + scp[1][tid]);
    }
}

// ---------------- alpha_k = S / (K * R_k), reset R -----------------------------------
__global__ void k_alpha(int first) {
    int t = threadIdx.x;           // 512
    float Rk = g_R[t];
    __shared__ float sm[512];
    float S;
    if (first) {
        sm[t] = Rk;
        __syncthreads();
        for (int o = 256; o > 0; o >>= 1) {
            if (t < o) sm[t] += sm[t + o];
            __syncthreads();
        }
        S = sm[0];
        if (t == 0) g_S = S;
    } else {
        S = g_S;
    }
    g_alpha[t] = S / (512.0f * Rk);
    g_R[t] = 0.0f;
}

// ---------------- fused sinkhorn iteration (512 blocks, 8 rows/warp) -----------------
__global__ void k_rcpass() {
    int wid = threadIdx.x >> 5, lane = threadIdx.x & 31;
    __shared__ float sc[8][512];

    float al[16];
    const float* ap = g_alpha + lane * 16;
#pragma unroll
    for (int j = 0; j < 16; j++) al[j] = ap[j];
    float S = g_S;

    float colp[16];
#pragma unroll
    for (int j = 0; j < 16; j++) colp[j] = 0.0f;

    int row0 = blockIdx.x * 64 + wid * 8;
#pragma unroll
    for (int r = 0; r < 8; r++) {
        int row = row0 + r;
        const uint4* pe = (const uint4*)(g_E + (size_t)row * KK + lane * 16);
        uint4 u0 = pe[0], u1 = pe[1];
        float ev[16];
        {
            __nv_bfloat162* h0 = (__nv_bfloat162*)&u0;
            __nv_bfloat162* h1 = (__nv_bfloat162*)&u1;
#pragma unroll
            for (int k = 0; k < 4; k++) {
                float2 f0 = __bfloat1622float2(h0[k]);
                float2 f1 = __bfloat1622float2(h1[k]);
                ev[k * 2 + 0] = f0.x; ev[k * 2 + 1] = f0.y;
                ev[8 + k * 2 + 0] = f1.x; ev[8 + k * 2 + 1] = f1.y;
            }
        }
        float dot = 0.0f;
#pragma unroll
        for (int j = 0; j < 16; j++) dot = fmaf(ev[j], al[j], dot);
#pragma unroll
        for (int o = 16; o > 0; o >>= 1) dot += __shfl_xor_sync(0xffffffffu, dot, o);
        float beta = S / (32768.0f * dot);
#pragma unroll
        for (int j = 0; j < 16; j++) colp[j] = fmaf(ev[j], beta, colp[j]);
    }
#pragma unroll
    for (int j = 0; j < 16; j++) sc[wid][lane * 16 + j] = colp[j];
    __syncthreads();
    for (int c = threadIdx.x; c < 512; c += 256) {
        float sum = sc[0][c] + sc[1][c] + sc[2][c] + sc[3][c]
                  + sc[4][c] + sc[5][c] + sc[6][c] + sc[7][c];
        atomicAdd(&g_R[c], sum);
    }
}

// ---------------- fused lse + loss (alpha derived from g_R in-register) ---------------
__global__ void k_loss() {
    int wid = threadIdx.x >> 5, lane = threadIdx.x & 31;
    __shared__ float sl[8];

    float S = g_S;
    float al[16];
    const float* rp = g_R + lane * 16;
#pragma unroll
    for (int j = 0; j < 16; j++) al[j] = S / (512.0f * rp[j]);

    float lacc = 0.0f;
    int row0 = blockIdx.x * 64 + wid * 8;
#pragma unroll
    for (int r = 0; r < 8; r++) {
        int row = row0 + r;
        const uint4* pe = (const uint4*)(g_E + (size_t)row * KK + lane * 16);
        const uint4* ps = (const uint4*)(g_Ss + (size_t)row * KK + lane * 16);
        uint4 ue0 = pe[0], ue1 = pe[1], us0 = ps[0], us1 = ps[1];
        float ev[16], v[16];
        {
            __nv_bfloat162* he0 = (__nv_bfloat162*)&ue0;
            __nv_bfloat162* he1 = (__nv_bfloat162*)&ue1;
            __nv_bfloat162* hs0 = (__nv_bfloat162*)&us0;
            __nv_bfloat162* hs1 = (__nv_bfloat162*)&us1;
#pragma unroll
            for (int k = 0; k < 4; k++) {
                float2 f0 = __bfloat1622float2(he0[k]);
                float2 f1 = __bfloat1622float2(he1[k]);
                ev[k * 2] = f0.x; ev[k * 2 + 1] = f0.y;
                ev[8 + k * 2] = f1.x; ev[8 + k * 2 + 1] = f1.y;
                float2 g0 = __bfloat1622float2(hs0[k]);
                float2 g1 = __bfloat1622float2(hs1[k]);
                v[k * 2] = g0.x * INV_T; v[k * 2 + 1] = g0.y * INV_T;
                v[8 + k * 2] = g1.x * INV_T; v[8 + k * 2 + 1] = g1.y * INV_T;
            }
        }
        float mx = v[0];
#pragma unroll
        for (int j = 1; j < 16; j++) mx = fmaxf(mx, v[j]);
#pragma unroll
        for (int o = 16; o > 0; o >>= 1)
            mx = fmaxf(mx, __shfl_xor_sync(0xffffffffu, mx, o));
        float se = 0.0f, C = 0.0f, Acc = 0.0f;
#pragma unroll
        for (int j = 0; j < 16; j++) {
            se += fexp(v[j] - mx);
            float q = ev[j] * al[j];
            C += q;
            Acc = fmaf(q, v[j], Acc);
        }
#pragma unroll
        for (int o = 16; o > 0; o >>= 1) {
            se += __shfl_xor_sync(0xffffffffu, se, o);
            C += __shfl_xor_sync(0xffffffffu, C, o);
            Acc += __shfl_xor_sync(0xffffffffu, Acc, o);
        }
        float lse = mx + logf(se);
        lacc += -(Acc - lse * C) / C;
    }
    if (lane == 0) sl[wid] = lacc;
    __syncthreads();
    if (threadIdx.x == 0) {
        float b = sl[0] + sl[1] + sl[2] + sl[3] + sl[4] + sl[5] + sl[6] + sl[7];
        atomicAdd(&g_loss, b);
    }
}

__global__ void k_final(float* __restrict__ out) {
    out[0] = g_loss * (1.0f / 32768.0f);
}

// ---------------- launch ---------------------------------------------------------------
#define GEMM_SMEM (STAGES * STAGE_BYTES)

extern "C" void kernel_launch(void* const* d_in, const int* in_sizes, int n_in,
                              void* d_out, int out_size) {
    const float* s = nullptr;
    const float* t = nullptr;
    const float* W_net = nullptr;
    const float* W_proto = nullptr;
    for (int i = 0; i < n_in; i++) {
        long long sz = in_sizes[i];
        if (sz == (long long)BB * DD) {
            if (!s) s = (const float*)d_in[i];
            else if (!t) t = (const float*)d_in[i];
        } else if (sz == (long long)KK * DD) {
            W_net = (const float*)d_in[i];
        } else if (sz == (long long)KK * KK) {
            W_proto = (const float*)d_in[i];
        }
    }
    float* out = (float*)d_out;

    __nv_bfloat16 *Ss, *E, *Zb, *W, *Cn;
    cudaGetSymbolAddress((void**)&Ss, g_Ss);
    cudaGetSymbolAddress((void**)&E, g_E);
    cudaGetSymbolAddress((void**)&Zb, g_Zb);
    cudaGetSymbolAddress((void**)&W, g_W);
    cudaGetSymbolAddress((void**)&Cn, g_Cn);

    cudaFuncSetAttribute(k_gemm1f, cudaFuncAttributeMaxDynamicSharedMemorySize, G1_SMEM);
    cudaFuncSetAttribute(k_gemm, cudaFuncAttributeMaxDynamicSharedMemorySize, GEMM_SMEM);

    dim3 gg(KK / 128, 2 * BB / 128);   // (4, 512) batched

    k_init<<<2 * BB / 512, 512>>>();
    k_proto<<<KK, 128>>>(W_proto);
    k_conv<<<512, 256>>>(W_net, W, (KK * DD) / 4);

    // batched: Zb = [s;t]@W^T (+ row sumsq); scores/E (invn inline)
    k_gemm1f<<<gg, 128, G1_SMEM>>>(s, t, W, Zb);
    k_gemm<<<gg, 256, GEMM_SMEM>>>(Zb, Cn, Ss, E);

    // sinkhorn (factor form, fused row+col passes)
    k_alpha<<<1, 512>>>(1);
    k_rcpass<<<512, 256>>>();
    k_alpha<<<1, 512>>>(0);
    k_rcpass<<<512, 256>>>();
    // alpha3 folded into k_loss

    // fused lse + loss
    k_loss<<<512, 256>>>();
    k_final<<<1, 1>>>(out);
}

// round 15
// speedup vs baseline: 1.1143x; 1.1143x over previous
#include <cuda_runtime.h>
#include <cuda_bf16.h>
#include <math.h>
#include <stdint.h>

#define BB 32768
#define DD 1024
#define KK 512
#define INV_T 10.0f

// ---------------- scratch (static device globals) ----------------------------
__device__ __align__(16) __nv_bfloat16 g_Ss[16777216];   // scores_s bf16
__device__ __align__(16) __nv_bfloat16 g_E[16777216];    // E bf16
__device__ __align__(16) __nv_bfloat16 g_Zb[33554432];   // Z bf16 (s, then t)
__device__ __align__(16) __nv_bfloat16 g_W[524288];      // W_net bf16
__device__ __align__(16) __nv_bfloat16 g_Cn[262144];     // normalized protos bf16
__device__ float g_ss[2 * BB];      // row sumsq of Z (both branches)
__device__ float g_R0[KK];          // colsums of E (from gemm2)
__device__ float g_R1[KK];          // after sinkhorn iter 1
__device__ float g_R2[KK];          // after sinkhorn iter 2
__device__ float g_loss;

// ---------------- helpers ------------------------------------------------------
__device__ __forceinline__ uint32_t smem_u32(const void* p) {
    uint32_t a;
    asm("{ .reg .u64 t; cvta.to.shared.u64 t, %1; cvt.u32.u64 %0, t; }"
        : "=r"(a) : "l"(p));
    return a;
}
__device__ __forceinline__ void cp_async16(uint32_t saddr, const void* g) {
    asm volatile("cp.async.cg.shared.global [%0], [%1], 16;"
                 :: "r"(saddr), "l"(g) : "memory");
}
__device__ __forceinline__ void ldsm_x4(uint32_t* r, uint32_t addr) {
    asm volatile("ldmatrix.sync.aligned.m8n8.x4.shared.b16 {%0,%1,%2,%3}, [%4];"
                 : "=r"(r[0]), "=r"(r[1]), "=r"(r[2]), "=r"(r[3]) : "r"(addr));
}
__device__ __forceinline__ void mma16816(float* c, const uint32_t* a,
                                         uint32_t b0, uint32_t b1) {
    asm volatile(
        "mma.sync.aligned.m16n8k16.row.col.f32.bf16.bf16.f32 "
        "{%0,%1,%2,%3}, {%4,%5,%6,%7}, {%8,%9}, {%0,%1,%2,%3};"
        : "+f"(c[0]), "+f"(c[1]), "+f"(c[2]), "+f"(c[3])
        : "r"(a[0]), "r"(a[1]), "r"(a[2]), "r"(a[3]), "r"(b0), "r"(b1));
}
#define SWZ(o) ((o) ^ (((o) >> 3) & 0x70))

// fast e^x on the FMA pipe (exp2-based, degree-6 poly, rel err ~6e-8)
__device__ __forceinline__ float fexp(float x) {
    float y = x * 1.4426950408889634f;
    float t = y + 12582912.0f;
    int e = __float_as_int(t) - 0x4B400000;
    float f = y - (t - 12582912.0f);
    float p = 1.5403530e-4f;
    p = fmaf(p, f, 1.3333558e-3f);
    p = fmaf(p, f, 9.6181291e-3f);
    p = fmaf(p, f, 5.5504109e-2f);
    p = fmaf(p, f, 2.4022651e-1f);
    p = fmaf(p, f, 6.9314718e-1f);
    p = fmaf(p, f, 1.0f);
    return p * __int_as_float((e + 127) << 23);
}

__device__ __forceinline__ __nv_bfloat162 pack2(float a, float b) {
    return __halves2bfloat162(__float2bfloat16(a), __float2bfloat16(b));
}

// block-wide sum of a 512-float device vector (256 threads), result broadcast
__device__ __forceinline__ float blocksum512(const float* v, float* sred) {
    int tid = threadIdx.x;
    float part = v[tid] + v[tid + 256];
#pragma unroll
    for (int o = 16; o > 0; o >>= 1)
        part += __shfl_xor_sync(0xffffffffu, part, o);
    if ((tid & 31) == 0) sred[tid >> 5] = part;
    __syncthreads();
    float S = sred[0] + sred[1] + sred[2] + sred[3]
            + sred[4] + sred[5] + sred[6] + sred[7];
    return S;
}

// ---------------- init ----------------------------------------------------------
__global__ void k_init() {
    int i = blockIdx.x * blockDim.x + threadIdx.x;     // 65536 threads
    g_ss[i] = 0.0f;
    if (i < KK) { g_R0[i] = 0.0f; g_R1[i] = 0.0f; g_R2[i] = 0.0f; }
    if (i == 0) g_loss = 0.0f;
}

// ---------------- Cn = l2norm rows of W_proto -> bf16 ---------------------------
__global__ void k_proto(const float* __restrict__ W) {
    int row = blockIdx.x;
    int t = threadIdx.x;
    float4 v = ((const float4*)(W + (size_t)row * KK))[t];
    float s = v.x * v.x + v.y * v.y + v.z * v.z + v.w * v.w;
    __shared__ float sm[128];
    sm[t] = s;
    __syncthreads();
    for (int o = 64; o > 0; o >>= 1) {
        if (t < o) sm[t] += sm[t + o];
        __syncthreads();
    }
    float inv = rsqrtf(sm[0]);
    __nv_bfloat162* hp = (__nv_bfloat162*)(g_Cn + (size_t)row * KK + t * 4);
    hp[0] = pack2(v.x * inv, v.y * inv);
    hp[1] = pack2(v.z * inv, v.w * inv);
}

// ---------------- f32 -> bf16 (W_net only; tiny) ----------------------------------
__global__ void k_conv(const float* __restrict__ x, __nv_bfloat16* __restrict__ hd,
                       int n4) {
    int i = blockIdx.x * blockDim.x + threadIdx.x;
    int stride = gridDim.x * blockDim.x;
    for (; i < n4; i += stride) {
        float4 v = ((const float4*)x)[i];
        __nv_bfloat162* hp = (__nv_bfloat162*)(hd + (size_t)i * 4);
        hp[0] = pack2(v.x, v.y);
        hp[1] = pack2(v.z, v.w);
    }
}

// ================= gemm1 batched (R13 config: 8 warps, 64x32 warp tiles) =========
#define G1_ABF 0
#define G1_BT 32768
#define G1_SMEM 65536
__global__ void __launch_bounds__(256, 2)
k_gemm1f(const float* __restrict__ S, const float* __restrict__ T,
         const __nv_bfloat16* __restrict__ B, __nv_bfloat16* __restrict__ C) {
    extern __shared__ char smem[];
    const int Kd = DD;          // 1024
    const int NT = Kd >> 6;     // 16 k-tiles

    int tid = threadIdx.x, wid = tid >> 5, lane = tid & 31;
    int by = blockIdx.y;
    const float* A = (by < 256) ? S : T;
    int am0 = (by & 255) * 128;
    int m0 = by * 128;
    int n0 = blockIdx.x * 128;
    int wm = wid >> 2, wn = wid & 3;

    uint32_t s_base = smem_u32(smem);

    int lrow = tid >> 3, lseg = tid & 7;
    const float* gA0 = A + (size_t)(am0 + lrow) * Kd + lseg * 4;
    const __nv_bfloat16* gB0 = B + (size_t)(n0 + lrow) * Kd + lseg * 8;

    auto loadB = [&](int kt, int st) {
        uint32_t sa = s_base + G1_BT + (uint32_t)st * 16384;
        int kc = kt * 64;
#pragma unroll
        for (int p = 0; p < 4; p++) {
            uint32_t so = SWZ((lrow + p * 32) * 128 + lseg * 16);
            cp_async16(sa + so, gB0 + (size_t)p * 32 * Kd + kc);
        }
        asm volatile("cp.async.commit_group;" ::: "memory");
    };

    float4 fb[4];
    auto ldgA = [&](int kt, int h) {
#pragma unroll
        for (int p = 0; p < 4; p++)
            fb[p] = *(const float4*)(gA0 + (size_t)p * 32 * Kd + kt * 64 + h * 32);
    };
    uint32_t stsAddr[4][2];
#pragma unroll
    for (int p = 0; p < 4; p++)
#pragma unroll
        for (int h = 0; h < 2; h++)
            stsAddr[p][h] = SWZ((uint32_t)((lrow + p * 32) * 128 + lseg * 8 + h * 64));
    auto stsA = [&](int st, int h) {
        uint32_t ab = s_base + G1_ABF + (uint32_t)st * 16384;
#pragma unroll
        for (int p = 0; p < 4; p++) {
            __nv_bfloat162 q0 = pack2(fb[p].x, fb[p].y);
            __nv_bfloat162 q1 = pack2(fb[p].z, fb[p].w);
            asm volatile("st.shared.v2.b32 [%0], {%1,%2};"
                         :: "r"(ab + stsAddr[p][h]),
                            "r"(*(uint32_t*)&q0), "r"(*(uint32_t*)&q1) : "memory");
        }
    };

    uint32_t offA[4], offB[2];
    {
        int rA = (lane & 7) + ((lane >> 3) & 1) * 8;
        int sA = (lane >> 4) * 16;
#pragma unroll
        for (int im = 0; im < 4; im++) {
            int row = wm * 64 + im * 16 + rA;
            offA[im] = (uint32_t)(row * 128) | (uint32_t)(sA ^ ((row & 7) << 4));
        }
        int rB = (lane & 7) + ((lane >> 4) & 1) * 8;
        int sB = ((lane >> 3) & 1) * 16;
#pragma unroll
        for (int j = 0; j < 2; j++) {
            int row = wn * 32 + j * 16 + rB;
            offB[j] = (uint32_t)(row * 128) | (uint32_t)(sB ^ ((row & 7) << 4));
        }
    }

    float acc[4][4][4];
#pragma unroll
    for (int i = 0; i < 4; i++)
#pragma unroll
        for (int j = 0; j < 4; j++)
#pragma unroll
            for (int k = 0; k < 4; k++) acc[i][j][k] = 0.0f;

    loadB(0, 0);
    ldgA(0, 0); stsA(0, 0);
    ldgA(0, 1); stsA(0, 1);
    asm volatile("cp.async.wait_group 0;" ::: "memory");
    __syncthreads();

    for (int kt = 0; kt < NT; kt++) {
        int st = kt & 1;
        bool more = (kt + 1 < NT);
        if (more) {
            loadB(kt + 1, st ^ 1);
            ldgA(kt + 1, 0);
        }
        uint32_t sbA = s_base + G1_ABF + (uint32_t)st * 16384;
        uint32_t sbB = s_base + G1_BT + (uint32_t)st * 16384;
#pragma unroll
        for (int ks = 0; ks < 2; ks++) {
            uint32_t kx = (uint32_t)(ks << 5);
            uint32_t a[4][4], b[2][4];
#pragma unroll
            for (int im = 0; im < 4; im++) ldsm_x4(a[im], sbA + (offA[im] ^ kx));
#pragma unroll
            for (int j = 0; j < 2; j++) ldsm_x4(b[j], sbB + (offB[j] ^ kx));
#pragma unroll
            for (int im = 0; im < 4; im++)
#pragma unroll
                for (int j = 0; j < 2; j++) {
                    mma16816(acc[im][j * 2 + 0], a[im], b[j][0], b[j][1]);
                    mma16816(acc[im][j * 2 + 1], a[im], b[j][2], b[j][3]);
                }
        }
        if (more) {
            stsA(st ^ 1, 0);
            ldgA(kt + 1, 1);
        }
#pragma unroll
        for (int ks = 2; ks < 4; ks++) {
            uint32_t kx = (uint32_t)(ks << 5);
            uint32_t a[4][4], b[2][4];
#pragma unroll
            for (int im = 0; im < 4; im++) ldsm_x4(a[im], sbA + (offA[im] ^ kx));
#pragma unroll
            for (int j = 0; j < 2; j++) ldsm_x4(b[j], sbB + (offB[j] ^ kx));
#pragma unroll
            for (int im = 0; im < 4; im++)
#pragma unroll
                for (int j = 0; j < 2; j++) {
                    mma16816(acc[im][j * 2 + 0], a[im], b[j][0], b[j][1]);
                    mma16816(acc[im][j * 2 + 1], a[im], b[j][2], b[j][3]);
                }
        }
        if (more) {
            stsA(st ^ 1, 1);
            asm volatile("cp.async.wait_group 0;" ::: "memory");
        }
        __syncthreads();
    }

    // ---- epilogue: bf16 out + row sumsq ----
#pragma unroll
    for (int im = 0; im < 4; im++) {
        int m = m0 + wm * 64 + im * 16 + (lane >> 2);
        float s0 = 0.0f, s1 = 0.0f;
#pragma unroll
        for (int jn = 0; jn < 4; jn++) {
            int n = n0 + wn * 32 + jn * 8 + (lane & 3) * 2;
            float c0 = acc[im][jn][0], c1 = acc[im][jn][1];
            float c2 = acc[im][jn][2], c3 = acc[im][jn][3];
            s0 += c0 * c0 + c1 * c1;
            s1 += c2 * c2 + c3 * c3;
            *(__nv_bfloat162*)(C + (size_t)m * KK + n) = pack2(c0, c1);
            *(__nv_bfloat162*)(C + (size_t)(m + 8) * KK + n) = pack2(c2, c3);
        }
        s0 += __shfl_xor_sync(0xffffffffu, s0, 1);
        s0 += __shfl_xor_sync(0xffffffffu, s0, 2);
        s1 += __shfl_xor_sync(0xffffffffu, s1, 1);
        s1 += __shfl_xor_sync(0xffffffffu, s1, 2);
        if ((lane & 3) == 0) {
            atomicAdd(&g_ss[m], s0);
            atomicAdd(&g_ss[m + 8], s1);
        }
    }
}

// ================= gemm2 batched: scores (student) / E (teacher, colsums->g_R0) ==
#define STAGES 3
#define STAGE_BYTES 32768
__global__ void __launch_bounds__(256, 2)
k_gemm(const __nv_bfloat16* __restrict__ A, const __nv_bfloat16* __restrict__ B,
       __nv_bfloat16* __restrict__ Cs, __nv_bfloat16* __restrict__ Ce) {
    extern __shared__ char smem[];
    __shared__ float scp[2][128];

    int tid = threadIdx.x, wid = tid >> 5, lane = tid & 31;
    int by = blockIdx.y;
    int m0 = by * 128;
    int n0 = blockIdx.x * 128;
    int teacher = (by >= 256);
    __nv_bfloat16* C = teacher ? (Ce + (size_t)(m0 - BB) * KK)
                               : (Cs + (size_t)m0 * KK);
    int wm = wid >> 2, wn = wid & 3;

    uint32_t s_base = smem_u32(smem);
    const int NT = KK >> 6;                  // 8

    int lrow = tid >> 3, lseg = tid & 7;
    const __nv_bfloat16* gA0 = A + (size_t)(m0 + lrow) * KK + lseg * 8;
    const __nv_bfloat16* gB0 = B + (size_t)(n0 + lrow) * KK + lseg * 8;
    auto load = [&](int kt, int st) {
        int kc = kt * 64;
        uint32_t sa = s_base + st * STAGE_BYTES;
#pragma unroll
        for (int p = 0; p < 4; p++) {
            uint32_t so = SWZ((lrow + p * 32) * 128 + lseg * 16);
            cp_async16(sa + so, gA0 + (size_t)p * 32 * KK + kc);
            cp_async16(sa + 16384 + so, gB0 + (size_t)p * 32 * KK + kc);
        }
        asm volatile("cp.async.commit_group;" ::: "memory");
    };

    uint32_t offA[4], offB[2];
    {
        int rA = (lane & 7) + ((lane >> 3) & 1) * 8;
        int sA = (lane >> 4) * 16;
#pragma unroll
        for (int im = 0; im < 4; im++) {
            int row = wm * 64 + im * 16 + rA;
            offA[im] = (uint32_t)(row * 128) | (uint32_t)(sA ^ ((row & 7) << 4));
        }
        int rB = (lane & 7) + ((lane >> 4) & 1) * 8;
        int sB = ((lane >> 3) & 1) * 16;
#pragma unroll
        for (int j = 0; j < 2; j++) {
            int row = wn * 32 + j * 16 + rB;
            offB[j] = 16384u + ((uint32_t)(row * 128) |
                                (uint32_t)(sB ^ ((row & 7) << 4)));
        }
    }

    float acc[4][4][4];
#pragma unroll
    for (int i = 0; i < 4; i++)
#pragma unroll
        for (int j = 0; j < 4; j++)
#pragma unroll
            for (int k = 0; k < 4; k++) acc[i][j][k] = 0.0f;

    load(0, 0);
    load(1, 1);

    for (int kt = 0; kt < NT; kt++) {
        asm volatile("cp.async.wait_group 1;" ::: "memory");
        __syncthreads();
        uint32_t sb = s_base + (uint32_t)(kt % 3) * STAGE_BYTES;
#pragma unroll
        for (int ks = 0; ks < 4; ks++) {
            uint32_t kx = (uint32_t)(ks << 5);
            uint32_t a[4][4], b[2][4];
#pragma unroll
            for (int im = 0; im < 4; im++) ldsm_x4(a[im], sb + (offA[im] ^ kx));
#pragma unroll
            for (int j = 0; j < 2; j++) ldsm_x4(b[j], sb + (offB[j] ^ kx));
#pragma unroll
            for (int im = 0; im < 4; im++)
#pragma unroll
                for (int j = 0; j < 2; j++) {
                    mma16816(acc[im][j * 2 + 0], a[im], b[j][0], b[j][1]);
                    mma16816(acc[im][j * 2 + 1], a[im], b[j][2], b[j][3]);
                }
        }
        if (kt + 2 < NT) load(kt + 2, (kt + 2) % 3);
        else asm volatile("cp.async.commit_group;" ::: "memory");
    }

    float ce0[4] = {0, 0, 0, 0}, ce1[4] = {0, 0, 0, 0};
#pragma unroll
    for (int im = 0; im < 4; im++) {
        int m = m0 + wm * 64 + im * 16 + (lane >> 2);
        int ml = wm * 64 + im * 16 + (lane >> 2);
        float i0 = rsqrtf(g_ss[m]), i1 = rsqrtf(g_ss[m + 8]);
#pragma unroll
        for (int jn = 0; jn < 4; jn++) {
            int n = n0 + wn * 32 + jn * 8 + (lane & 3) * 2;
            float c0 = acc[im][jn][0] * i0, c1 = acc[im][jn][1] * i0;
            float c2 = acc[im][jn][2] * i1, c3 = acc[im][jn][3] * i1;
            if (teacher) {
                c0 = fexp((c0 - 1.0f) * INV_T);
                c1 = fexp((c1 - 1.0f) * INV_T);
                c2 = fexp((c2 - 1.0f) * INV_T);
                c3 = fexp((c3 - 1.0f) * INV_T);
                ce0[jn] += c0 + c2;
                ce1[jn] += c1 + c3;
            }
            *(__nv_bfloat162*)(C + (size_t)ml * KK + n) = pack2(c0, c1);
            *(__nv_bfloat162*)(C + (size_t)(ml + 8) * KK + n) = pack2(c2, c3);
        }
    }
    if (teacher) {
#pragma unroll
        for (int jn = 0; jn < 4; jn++) {
#pragma unroll
            for (int o = 4; o < 32; o <<= 1) {
                ce0[jn] += __shfl_xor_sync(0xffffffffu, ce0[jn], o);
                ce1[jn] += __shfl_xor_sync(0xffffffffu, ce1[jn], o);
            }
        }
        if (lane < 4) {
#pragma unroll
            for (int jn = 0; jn < 4; jn++) {
                scp[wm][wn * 32 + jn * 8 + lane * 2 + 0] = ce0[jn];
                scp[wm][wn * 32 + jn * 8 + lane * 2 + 1] = ce1[jn];
            }
        }
        __syncthreads();
        if (tid < 128)
            atomicAdd(&g_R0[n0 + tid], scp[0][tid] + scp[1][tid]);
    }
}

// ---------------- fused sinkhorn iteration (self-contained alpha) --------------------
// reads inR (colsums), computes S + alpha in-block, accumulates new colsums -> outR.
__global__ void k_rcpass(const float* __restrict__ inR, float* __restrict__ outR) {
    int tid = threadIdx.x, wid = tid >> 5, lane = tid & 31;
    __shared__ float sc[8][512];
    __shared__ float sred[8];

    float S = blocksum512(inR, sred);

    float al[16];
    const float* ap = inR + lane * 16;
#pragma unroll
    for (int j = 0; j < 16; j++) al[j] = S / (512.0f * ap[j]);

    float colp[16];
#pragma unroll
    for (int j = 0; j < 16; j++) colp[j] = 0.0f;

    int row0 = blockIdx.x * 64 + wid * 8;
#pragma unroll
    for (int r = 0; r < 8; r++) {
        int row = row0 + r;
        const uint4* pe = (const uint4*)(g_E + (size_t)row * KK + lane * 16);
        uint4 u0 = pe[0], u1 = pe[1];
        float ev[16];
        {
            __nv_bfloat162* h0 = (__nv_bfloat162*)&u0;
            __nv_bfloat162* h1 = (__nv_bfloat162*)&u1;
#pragma unroll
            for (int k = 0; k < 4; k++) {
                float2 f0 = __bfloat1622float2(h0[k]);
                float2 f1 = __bfloat1622float2(h1[k]);
                ev[k * 2 + 0] = f0.x; ev[k * 2 + 1] = f0.y;
                ev[8 + k * 2 + 0] = f1.x; ev[8 + k * 2 + 1] = f1.y;
            }
        }
        float dot = 0.0f;
#pragma unroll
        for (int j = 0; j < 16; j++) dot = fmaf(ev[j], al[j], dot);
#pragma unroll
        for (int o = 16; o > 0; o >>= 1) dot += __shfl_xor_sync(0xffffffffu, dot, o);
        float beta = S / (32768.0f * dot);
#pragma unroll
        for (int j = 0; j < 16; j++) colp[j] = fmaf(ev[j], beta, colp[j]);
    }
#pragma unroll
    for (int j = 0; j < 16; j++) sc[wid][lane * 16 + j] = colp[j];
    __syncthreads();
    for (int c = tid; c < 512; c += 256) {
        float sum = sc[0][c] + sc[1][c] + sc[2][c] + sc[3][c]
                  + sc[4][c] + sc[5][c] + sc[6][c] + sc[7][c];
        atomicAdd(&outR[c], sum);
    }
}

// ---------------- fused lse + loss (S from g_R0, alpha from g_R2) ---------------------
__global__ void k_loss() {
    int tid = threadIdx.x, wid = tid >> 5, lane = tid & 31;
    __shared__ float sl[8];
    __shared__ float sred[8];

    float S = blocksum512(g_R0, sred);

    float al[16];
    const float* rp = g_R2 + lane * 16;
#pragma unroll
    for (int j = 0; j < 16; j++) al[j] = S / (512.0f * rp[j]);

    float lacc = 0.0f;
    int row0 = blockIdx.x * 64 + wid * 8;
#pragma unroll
    for (int r = 0; r < 8; r++) {
        int row = row0 + r;
        const uint4* pe = (const uint4*)(g_E + (size_t)row * KK + lane * 16);
        const uint4* ps = (const uint4*)(g_Ss + (size_t)row * KK + lane * 16);
        uint4 ue0 = pe[0], ue1 = pe[1], us0 = ps[0], us1 = ps[1];
        float ev[16], v[16];
        {
            __nv_bfloat162* he0 = (__nv_bfloat162*)&ue0;
            __nv_bfloat162* he1 = (__nv_bfloat162*)&ue1;
            __nv_bfloat162* hs0 = (__nv_bfloat162*)&us0;
            __nv_bfloat162* hs1 = (__nv_bfloat162*)&us1;
#pragma unroll
            for (int k = 0; k < 4; k++) {
                float2 f0 = __bfloat1622float2(he0[k]);
                float2 f1 = __bfloat1622float2(he1[k]);
                ev[k * 2] = f0.x; ev[k * 2 + 1] = f0.y;
                ev[8 + k * 2] = f1.x; ev[8 + k * 2 + 1] = f1.y;
                float2 g0 = __bfloat1622float2(hs0[k]);
                float2 g1 = __bfloat1622float2(hs1[k]);
                v[k * 2] = g0.x * INV_T; v[k * 2 + 1] = g0.y * INV_T;
                v[8 + k * 2] = g1.x * INV_T; v[8 + k * 2 + 1] = g1.y * INV_T;
            }
        }
        float mx = v[0];
#pragma unroll
        for (int j = 1; j < 16; j++) mx = fmaxf(mx, v[j]);
#pragma unroll
        for (int o = 16; o > 0; o >>= 1)
            mx = fmaxf(mx, __shfl_xor_sync(0xffffffffu, mx, o));
        float se = 0.0f, C = 0.0f, Acc = 0.0f;
#pragma unroll
        for (int j = 0; j < 16; j++) {
            se += fexp(v[j] - mx);
            float q = ev[j] * al[j];
            C += q;
            Acc = fmaf(q, v[j], Acc);
        }
#pragma unroll
        for (int o = 16; o > 0; o >>= 1) {
            se += __shfl_xor_sync(0xffffffffu, se, o);
            C += __shfl_xor_sync(0xffffffffu, C, o);
            Acc += __shfl_xor_sync(0xffffffffu, Acc, o);
        }
        float lse = mx + logf(se);
        lacc += -(Acc - lse * C) / C;
    }
    if (lane == 0) sl[wid] = lacc;
    __syncthreads();
    if (tid == 0) {
        float b = sl[0] + sl[1] + sl[2] + sl[3] + sl[4] + sl[5] + sl[6] + sl[7];
        atomicAdd(&g_loss, b);
    }
}

__global__ void k_final(float* __restrict__ out) {
    out[0] = g_loss * (1.0f / 32768.0f);
}

// ---------------- launch ---------------------------------------------------------------
#define GEMM_SMEM (STAGES * STAGE_BYTES)

extern "C" void kernel_launch(void* const* d_in, const int* in_sizes, int n_in,
                              void* d_out, int out_size) {
    const float* s = nullptr;
    const float* t = nullptr;
    const float* W_net = nullptr;
    const float* W_proto = nullptr;
    for (int i = 0; i < n_in; i++) {
        long long sz = in_sizes[i];
        if (sz == (long long)BB * DD) {
            if (!s) s = (const float*)d_in[i];
            else if (!t) t = (const float*)d_in[i];
        } else if (sz == (long long)KK * DD) {
            W_net = (const float*)d_in[i];
        } else if (sz == (long long)KK * KK) {
            W_proto = (const float*)d_in[i];
        }
    }
    float* out = (float*)d_out;

    __nv_bfloat16 *Ss, *E, *Zb, *W, *Cn;
    float *R0, *R1, *R2;
    cudaGetSymbolAddress((void**)&Ss, g_Ss);
    cudaGetSymbolAddress((void**)&E, g_E);
    cudaGetSymbolAddress((void**)&Zb, g_Zb);
    cudaGetSymbolAddress((void**)&W, g_W);
    cudaGetSymbolAddress((void**)&Cn, g_Cn);
    cudaGetSymbolAddress((void**)&R0, g_R0);
    cudaGetSymbolAddress((void**)&R1, g_R1);
    cudaGetSymbolAddress((void**)&R2, g_R2);

    cudaFuncSetAttribute(k_gemm1f, cudaFuncAttributeMaxDynamicSharedMemorySize, G1_SMEM);
    cudaFuncSetAttribute(k_gemm, cudaFuncAttributeMaxDynamicSharedMemorySize, GEMM_SMEM);

    dim3 gg(KK / 128, 2 * BB / 128);   // (4, 512) batched

    k_init<<<2 * BB / 512, 512>>>();
    k_proto<<<KK, 128>>>(W_proto);
    k_conv<<<512, 256>>>(W_net, W, (KK * DD) / 4);

    // batched: Zb = [s;t]@W^T (+ row sumsq); scores/E (invn inline, colsums->R0)
    k_gemm1f<<<gg, 256, G1_SMEM>>>(s, t, W, Zb);
    k_gemm<<<gg, 256, GEMM_SMEM>>>(Zb, Cn, Ss, E);

    // sinkhorn: two fused iterations, alpha computed in-block (no k_alpha kernels)
    k_rcpass<<<512, 256>>>(R0, R1);
    k_rcpass<<<512, 256>>>(R1, R2);

    // fused lse + loss (alpha3 from R2, S from R0)
    k_loss<<<512, 256>>>();
    k_final<<<1, 1>>>(out);
}

// round 17
// speedup vs baseline: 1.1537x; 1.0354x over previous
#include <cuda_runtime.h>
#include <cuda_bf16.h>
#include <math.h>
#include <stdint.h>

#define BB 32768
#define DD 1024
#define KK 512
#define INV_T 10.0f
#define SINK_GRID 296

// ---------------- scratch (static device globals) ----------------------------
__device__ __align__(16) __nv_bfloat16 g_Ss[16777216];   // scores_s bf16
__device__ __align__(16) __nv_bfloat16 g_E[16777216];    // E bf16
__device__ __align__(16) __nv_bfloat16 g_Zb[33554432];   // Z bf16 (s, then t)
__device__ __align__(16) __nv_bfloat16 g_W[524288];      // W_net bf16
__device__ __align__(16) __nv_bfloat16 g_Cn[262144];     // normalized protos bf16
__device__ float g_ss[2 * BB];      // row sumsq of Z (both branches)
__device__ float g_R0[KK];          // colsums of E (from gemm2)
__device__ float g_R1[KK];          // after sinkhorn iter 1
__device__ float g_R2[KK];          // after sinkhorn iter 2
__device__ float g_loss;
__device__ unsigned g_bar;

// ---------------- helpers ------------------------------------------------------
__device__ __forceinline__ uint32_t smem_u32(const void* p) {
    uint32_t a;
    asm("{ .reg .u64 t; cvta.to.shared.u64 t, %1; cvt.u32.u64 %0, t; }"
        : "=r"(a) : "l"(p));
    return a;
}
__device__ __forceinline__ void cp_async16(uint32_t saddr, const void* g) {
    asm volatile("cp.async.cg.shared.global [%0], [%1], 16;"
                 :: "r"(saddr), "l"(g) : "memory");
}
__device__ __forceinline__ void ldsm_x4(uint32_t* r, uint32_t addr) {
    asm volatile("ldmatrix.sync.aligned.m8n8.x4.shared.b16 {%0,%1,%2,%3}, [%4];"
                 : "=r"(r[0]), "=r"(r[1]), "=r"(r[2]), "=r"(r[3]) : "r"(addr));
}
__device__ __forceinline__ void mma16816(float* c, const uint32_t* a,
                                         uint32_t b0, uint32_t b1) {
    asm volatile(
        "mma.sync.aligned.m16n8k16.row.col.f32.bf16.bf16.f32 "
        "{%0,%1,%2,%3}, {%4,%5,%6,%7}, {%8,%9}, {%0,%1,%2,%3};"
        : "+f"(c[0]), "+f"(c[1]), "+f"(c[2]), "+f"(c[3])
        : "r"(a[0]), "r"(a[1]), "r"(a[2]), "r"(a[3]), "r"(b0), "r"(b1));
}
#define SWZ(o) ((o) ^ (((o) >> 3) & 0x70))

// fast e^x on the FMA pipe (exp2-based, degree-6 poly, rel err ~6e-8)
__device__ __forceinline__ float fexp(float x) {
    float y = x * 1.4426950408889634f;
    float t = y + 12582912.0f;
    int e = __float_as_int(t) - 0x4B400000;
    float f = y - (t - 12582912.0f);
    float p = 1.5403530e-4f;
    p = fmaf(p, f, 1.3333558e-3f);
    p = fmaf(p, f, 9.6181291e-3f);
    p = fmaf(p, f, 5.5504109e-2f);
    p = fmaf(p, f, 2.4022651e-1f);
    p = fmaf(p, f, 6.9314718e-1f);
    p = fmaf(p, f, 1.0f);
    return p * __int_as_float((e + 127) << 23);
}

__device__ __forceinline__ __nv_bfloat162 pack2(float a, float b) {
    return __halves2bfloat162(__float2bfloat16(a), __float2bfloat16(b));
}

// block-wide sum of a 512-float device vector (256 threads), result broadcast
__device__ __forceinline__ float blocksum512(const float* v, float* sred) {
    int tid = threadIdx.x;
    float part = v[tid] + v[tid + 256];
#pragma unroll
    for (int o = 16; o > 0; o >>= 1)
        part += __shfl_xor_sync(0xffffffffu, part, o);
    if ((tid & 31) == 0) sred[tid >> 5] = part;
    __syncthreads();
    float S = sred[0] + sred[1] + sred[2] + sred[3]
            + sred[4] + sred[5] + sred[6] + sred[7];
    return S;
}

// ---------------- setup: proto-normalize + W conv + zero-init (one launch) -------
__global__ void k_setup(const float* __restrict__ Wp, const float* __restrict__ Wn) {
    int bid = blockIdx.x, tid = threadIdx.x;
    if (bid < 256) {
        // proto: 2 rows per block (tid>>7 selects half)
        int half = tid >> 7, t = tid & 127;
        int row = bid * 2 + half;
        float4 v = ((const float4*)(Wp + (size_t)row * KK))[t];
        float s = v.x * v.x + v.y * v.y + v.z * v.z + v.w * v.w;
#pragma unroll
        for (int o = 16; o > 0; o >>= 1) s += __shfl_xor_sync(0xffffffffu, s, o);
        __shared__ float wsum[8];
        if ((tid & 31) == 0) wsum[tid >> 5] = s;
        __syncthreads();
        float tot = wsum[half * 4] + wsum[half * 4 + 1]
                  + wsum[half * 4 + 2] + wsum[half * 4 + 3];
        float inv = rsqrtf(tot);
        __nv_bfloat162* hp = (__nv_bfloat162*)(g_Cn + (size_t)row * KK + t * 4);
        hp[0] = pack2(v.x * inv, v.y * inv);
        hp[1] = pack2(v.z * inv, v.w * inv);
    } else if (bid < 768) {
        // W_net f32 -> bf16: 512 blocks x 256 = 131072 float4 chunks
        int i = (bid - 256) * 256 + tid;
        float4 v = ((const float4*)Wn)[i];
        __nv_bfloat162* hp = (__nv_bfloat162*)(g_W + (size_t)i * 4);
        hp[0] = pack2(v.x, v.y);
        hp[1] = pack2(v.z, v.w);
    } else {
        // init: 256 blocks x 256 = 65536
        int i = (bid - 768) * 256 + tid;
        g_ss[i] = 0.0f;
        if (i < KK) { g_R0[i] = 0.0f; g_R1[i] = 0.0f; g_R2[i] = 0.0f; }
        if (i == 0) { g_loss = 0.0f; g_bar = 0u; }
    }
}

// ================= gemm1 batched (8 warps, 64x32 warp tiles) =====================
#define G1_ABF 0
#define G1_BT 32768
#define G1_SMEM 65536
__global__ void __launch_bounds__(256, 2)
k_gemm1f(const float* __restrict__ S, const float* __restrict__ T,
         const __nv_bfloat16* __restrict__ B, __nv_bfloat16* __restrict__ C) {
    extern __shared__ char smem[];
    const int Kd = DD;          // 1024
    const int NT = Kd >> 6;     // 16 k-tiles

    int tid = threadIdx.x, wid = tid >> 5, lane = tid & 31;
    int by = blockIdx.y;
    const float* A = (by < 256) ? S : T;
    int am0 = (by & 255) * 128;
    int m0 = by * 128;
    int n0 = blockIdx.x * 128;
    int wm = wid >> 2, wn = wid & 3;

    uint32_t s_base = smem_u32(smem);

    int lrow = tid >> 3, lseg = tid & 7;
    const float* gA0 = A + (size_t)(am0 + lrow) * Kd + lseg * 4;
    const __nv_bfloat16* gB0 = B + (size_t)(n0 + lrow) * Kd + lseg * 8;

    auto loadB = [&](int kt, int st) {
        uint32_t sa = s_base + G1_BT + (uint32_t)st * 16384;
        int kc = kt * 64;
#pragma unroll
        for (int p = 0; p < 4; p++) {
            uint32_t so = SWZ((lrow + p * 32) * 128 + lseg * 16);
            cp_async16(sa + so, gB0 + (size_t)p * 32 * Kd + kc);
        }
        asm volatile("cp.async.commit_group;" ::: "memory");
    };

    float4 fb[4];
    auto ldgA = [&](int kt, int h) {
#pragma unroll
        for (int p = 0; p < 4; p++)
            fb[p] = *(const float4*)(gA0 + (size_t)p * 32 * Kd + kt * 64 + h * 32);
    };
    uint32_t stsAddr[4][2];
#pragma unroll
    for (int p = 0; p < 4; p++)
#pragma unroll
        for (int h = 0; h < 2; h++)
            stsAddr[p][h] = SWZ((uint32_t)((lrow + p * 32) * 128 + lseg * 8 + h * 64));
    auto stsA = [&](int st, int h) {
        uint32_t ab = s_base + G1_ABF + (uint32_t)st * 16384;
#pragma unroll
        for (int p = 0; p < 4; p++) {
            __nv_bfloat162 q0 = pack2(fb[p].x, fb[p].y);
            __nv_bfloat162 q1 = pack2(fb[p].z, fb[p].w);
            asm volatile("st.shared.v2.b32 [%0], {%1,%2};"
                         :: "r"(ab + stsAddr[p][h]),
                            "r"(*(uint32_t*)&q0), "r"(*(uint32_t*)&q1) : "memory");
        }
    };

    uint32_t offA[4], offB[2];
    {
        int rA = (lane & 7) + ((lane >> 3) & 1) * 8;
        int sA = (lane >> 4) * 16;
#pragma unroll
        for (int im = 0; im < 4; im++) {
            int row = wm * 64 + im * 16 + rA;
            offA[im] = (uint32_t)(row * 128) | (uint32_t)(sA ^ ((row & 7) << 4));
        }
        int rB = (lane & 7) + ((lane >> 4) & 1) * 8;
        int sB = ((lane >> 3) & 1) * 16;
#pragma unroll
        for (int j = 0; j < 2; j++) {
            int row = wn * 32 + j * 16 + rB;
            offB[j] = (uint32_t)(row * 128) | (uint32_t)(sB ^ ((row & 7) << 4));
        }
    }

    float acc[4][4][4];
#pragma unroll
    for (int i = 0; i < 4; i++)
#pragma unroll
        for (int j = 0; j < 4; j++)
#pragma unroll
            for (int k = 0; k < 4; k++) acc[i][j][k] = 0.0f;

    loadB(0, 0);
    ldgA(0, 0); stsA(0, 0);
    ldgA(0, 1); stsA(0, 1);
    asm volatile("cp.async.wait_group 0;" ::: "memory");
    __syncthreads();

    for (int kt = 0; kt < NT; kt++) {
        int st = kt & 1;
        bool more = (kt + 1 < NT);
        if (more) {
            loadB(kt + 1, st ^ 1);
            ldgA(kt + 1, 0);
        }
        uint32_t sbA = s_base + G1_ABF + (uint32_t)st * 16384;
        uint32_t sbB = s_base + G1_BT + (uint32_t)st * 16384;
#pragma unroll
        for (int ks = 0; ks < 2; ks++) {
            uint32_t kx = (uint32_t)(ks << 5);
            uint32_t a[4][4], b[2][4];
#pragma unroll
            for (int im = 0; im < 4; im++) ldsm_x4(a[im], sbA + (offA[im] ^ kx));
#pragma unroll
            for (int j = 0; j < 2; j++) ldsm_x4(b[j], sbB + (offB[j] ^ kx));
#pragma unroll
            for (int im = 0; im < 4; im++)
#pragma unroll
                for (int j = 0; j < 2; j++) {
                    mma16816(acc[im][j * 2 + 0], a[im], b[j][0], b[j][1]);
                    mma16816(acc[im][j * 2 + 1], a[im], b[j][2], b[j][3]);
                }
        }
        if (more) {
            stsA(st ^ 1, 0);
            ldgA(kt + 1, 1);
        }
#pragma unroll
        for (int ks = 2; ks < 4; ks++) {
            uint32_t kx = (uint32_t)(ks << 5);
            uint32_t a[4][4], b[2][4];
#pragma unroll
            for (int im = 0; im < 4; im++) ldsm_x4(a[im], sbA + (offA[im] ^ kx));
#pragma unroll
            for (int j = 0; j < 2; j++) ldsm_x4(b[j], sbB + (offB[j] ^ kx));
#pragma unroll
            for (int im = 0; im < 4; im++)
#pragma unroll
                for (int j = 0; j < 2; j++) {
                    mma16816(acc[im][j * 2 + 0], a[im], b[j][0], b[j][1]);
                    mma16816(acc[im][j * 2 + 1], a[im], b[j][2], b[j][3]);
                }
        }
        if (more) {
            stsA(st ^ 1, 1);
            asm volatile("cp.async.wait_group 0;" ::: "memory");
        }
        __syncthreads();
    }

    // ---- epilogue: bf16 out + row sumsq ----
#pragma unroll
    for (int im = 0; im < 4; im++) {
        int m = m0 + wm * 64 + im * 16 + (lane >> 2);
        float s0 = 0.0f, s1 = 0.0f;
#pragma unroll
        for (int jn = 0; jn < 4; jn++) {
            int n = n0 + wn * 32 + jn * 8 + (lane & 3) * 2;
            float c0 = acc[im][jn][0], c1 = acc[im][jn][1];
            float c2 = acc[im][jn][2], c3 = acc[im][jn][3];
            s0 += c0 * c0 + c1 * c1;
            s1 += c2 * c2 + c3 * c3;
            *(__nv_bfloat162*)(C + (size_t)m * KK + n) = pack2(c0, c1);
            *(__nv_bfloat162*)(C + (size_t)(m + 8) * KK + n) = pack2(c2, c3);
        }
        s0 += __shfl_xor_sync(0xffffffffu, s0, 1);
        s0 += __shfl_xor_sync(0xffffffffu, s0, 2);
        s1 += __shfl_xor_sync(0xffffffffu, s1, 1);
        s1 += __shfl_xor_sync(0xffffffffu, s1, 2);
        if ((lane & 3) == 0) {
            atomicAdd(&g_ss[m], s0);
            atomicAdd(&g_ss[m + 8], s1);
        }
    }
}

// ================= gemm2 batched: scores (student) / E (teacher, colsums->g_R0) ==
#define STAGES 3
#define STAGE_BYTES 32768
__global__ void __launch_bounds__(256, 2)
k_gemm(const __nv_bfloat16* __restrict__ A, const __nv_bfloat16* __restrict__ B,
       __nv_bfloat16* __restrict__ Cs, __nv_bfloat16* __restrict__ Ce) {
    extern __shared__ char smem[];
    __shared__ float scp[2][128];

    int tid = threadIdx.x, wid = tid >> 5, lane = tid & 31;
    int by = blockIdx.y;
    int m0 = by * 128;
    int n0 = blockIdx.x * 128;
    int teacher = (by >= 256);
    __nv_bfloat16* C = teacher ? (Ce + (size_t)(m0 - BB) * KK)
                               : (Cs + (size_t)m0 * KK);
    int wm = wid >> 2, wn = wid & 3;

    uint32_t s_base = smem_u32(smem);
    const int NT = KK >> 6;                  // 8

    int lrow = tid >> 3, lseg = tid & 7;
    const __nv_bfloat16* gA0 = A + (size_t)(m0 + lrow) * KK + lseg * 8;
    const __nv_bfloat16* gB0 = B + (size_t)(n0 + lrow) * KK + lseg * 8;
    auto load = [&](int kt, int st) {
        int kc = kt * 64;
        uint32_t sa = s_base + st * STAGE_BYTES;
#pragma unroll
        for (int p = 0; p < 4; p++) {
            uint32_t so = SWZ((lrow + p * 32) * 128 + lseg * 16);
            cp_async16(sa + so, gA0 + (size_t)p * 32 * KK + kc);
            cp_async16(sa + 16384 + so, gB0 + (size_t)p * 32 * KK + kc);
        }
        asm volatile("cp.async.commit_group;" ::: "memory");
    };

    uint32_t offA[4], offB[2];
    {
        int rA = (lane & 7) + ((lane >> 3) & 1) * 8;
        int sA = (lane >> 4) * 16;
#pragma unroll
        for (int im = 0; im < 4; im++) {
            int row = wm * 64 + im * 16 + rA;
            offA[im] = (uint32_t)(row * 128) | (uint32_t)(sA ^ ((row & 7) << 4));
        }
        int rB = (lane & 7) + ((lane >> 4) & 1) * 8;
        int sB = ((lane >> 3) & 1) * 16;
#pragma unroll
        for (int j = 0; j < 2; j++) {
            int row = wn * 32 + j * 16 + rB;
            offB[j] = 16384u + ((uint32_t)(row * 128) |
                                (uint32_t)(sB ^ ((row & 7) << 4)));
        }
    }

    float acc[4][4][4];
#pragma unroll
    for (int i = 0; i < 4; i++)
#pragma unroll
        for (int j = 0; j < 4; j++)
#pragma unroll
            for (int k = 0; k < 4; k++) acc[i][j][k] = 0.0f;

    load(0, 0);
    load(1, 1);

    for (int kt = 0; kt < NT; kt++) {
        asm volatile("cp.async.wait_group 1;" ::: "memory");
        __syncthreads();
        uint32_t sb = s_base + (uint32_t)(kt % 3) * STAGE_BYTES;
#pragma unroll
        for (int ks = 0; ks < 4; ks++) {
            uint32_t kx = (uint32_t)(ks << 5);
            uint32_t a[4][4], b[2][4];
#pragma unroll
            for (int im = 0; im < 4; im++) ldsm_x4(a[im], sb + (offA[im] ^ kx));
#pragma unroll
            for (int j = 0; j < 2; j++) ldsm_x4(b[j], sb + (offB[j] ^ kx));
#pragma unroll
            for (int im = 0; im < 4; im++)
#pragma unroll
                for (int j = 0; j < 2; j++) {
                    mma16816(acc[im][j * 2 + 0], a[im], b[j][0], b[j][1]);
                    mma16816(acc[im][j * 2 + 1], a[im], b[j][2], b[j][3]);
                }
        }
        if (kt + 2 < NT) load(kt + 2, (kt + 2) % 3);
        else asm volatile("cp.async.commit_group;" ::: "memory");
    }

    float ce0[4] = {0, 0, 0, 0}, ce1[4] = {0, 0, 0, 0};
#pragma unroll
    for (int im = 0; im < 4; im++) {
        int m = m0 + wm * 64 + im * 16 + (lane >> 2);
        int ml = wm * 64 + im * 16 + (lane >> 2);
        float i0 = rsqrtf(g_ss[m]), i1 = rsqrtf(g_ss[m + 8]);
#pragma unroll
        for (int jn = 0; jn < 4; jn++) {
            int n = n0 + wn * 32 + jn * 8 + (lane & 3) * 2;
            float c0 = acc[im][jn][0] * i0, c1 = acc[im][jn][1] * i0;
            float c2 = acc[im][jn][2] * i1, c3 = acc[im][jn][3] * i1;
            if (teacher) {
                c0 = fexp((c0 - 1.0f) * INV_T);
                c1 = fexp((c1 - 1.0f) * INV_T);
                c2 = fexp((c2 - 1.0f) * INV_T);
                c3 = fexp((c3 - 1.0f) * INV_T);
                ce0[jn] += c0 + c2;
                ce1[jn] += c1 + c3;
            }
            *(__nv_bfloat162*)(C + (size_t)ml * KK + n) = pack2(c0, c1);
            *(__nv_bfloat162*)(C + (size_t)(ml + 8) * KK + n) = pack2(c2, c3);
        }
    }
    if (teacher) {
#pragma unroll
        for (int jn = 0; jn < 4; jn++) {
#pragma unroll
            for (int o = 4; o < 32; o <<= 1) {
                ce0[jn] += __shfl_xor_sync(0xffffffffu, ce0[jn], o);
                ce1[jn] += __shfl_xor_sync(0xffffffffu, ce1[jn], o);
            }
        }
        if (lane < 4) {
#pragma unroll
            for (int jn = 0; jn < 4; jn++) {
                scp[wm][wn * 32 + jn * 8 + lane * 2 + 0] = ce0[jn];
                scp[wm][wn * 32 + jn * 8 + lane * 2 + 1] = ce1[jn];
            }
        }
        __syncthreads();
        if (tid < 128)
            atomicAdd(&g_R0[n0 + tid], scp[0][tid] + scp[1][tid]);
    }
}

// ================= persistent sinkhorn + loss (grid barrier) ======================
// phase0: R0->R1, phase1: R1->R2, phase2: loss. All 296 CTAs resident (occ 2).
__global__ void __launch_bounds__(256, 2) k_sink() {
    int tid = threadIdx.x, wid = tid >> 5, lane = tid & 31;
    __shared__ float sc[8][512];
    __shared__ float sred[8];
    unsigned NC = gridDim.x;

#pragma unroll 1
    for (int it = 0; it < 2; it++) {
        const float* inR = it ? g_R1 : g_R0;
        float* outR = it ? g_R2 : g_R1;
        float S = blocksum512(inR, sred);

        float al[16];
        const float* ap = inR + lane * 16;
#pragma unroll
        for (int j = 0; j < 16; j++) al[j] = S / (512.0f * ap[j]);

        float colp[16];
#pragma unroll
        for (int j = 0; j < 16; j++) colp[j] = 0.0f;

        for (int base = blockIdx.x * 64; base < BB; base += (int)NC * 64) {
            int row0 = base + wid * 8;
#pragma unroll
            for (int r = 0; r < 8; r++) {
                int row = row0 + r;
                const uint4* pe = (const uint4*)(g_E + (size_t)row * KK + lane * 16);
                uint4 u0 = pe[0], u1 = pe[1];
                float ev[16];
                {
                    __nv_bfloat162* h0 = (__nv_bfloat162*)&u0;
                    __nv_bfloat162* h1 = (__nv_bfloat162*)&u1;
#pragma unroll
                    for (int k = 0; k < 4; k++) {
                        float2 f0 = __bfloat1622float2(h0[k]);
                        float2 f1 = __bfloat1622float2(h1[k]);
                        ev[k * 2 + 0] = f0.x; ev[k * 2 + 1] = f0.y;
                        ev[8 + k * 2 + 0] = f1.x; ev[8 + k * 2 + 1] = f1.y;
                    }
                }
                float dot = 0.0f;
#pragma unroll
                for (int j = 0; j < 16; j++) dot = fmaf(ev[j], al[j], dot);
#pragma unroll
                for (int o = 16; o > 0; o >>= 1)
                    dot += __shfl_xor_sync(0xffffffffu, dot, o);
                float beta = S / (32768.0f * dot);
#pragma unroll
                for (int j = 0; j < 16; j++) colp[j] = fmaf(ev[j], beta, colp[j]);
            }
        }
        __syncthreads();
#pragma unroll
        for (int j = 0; j < 16; j++) sc[wid][lane * 16 + j] = colp[j];
        __syncthreads();
        for (int c = tid; c < 512; c += 256) {
            float sum = sc[0][c] + sc[1][c] + sc[2][c] + sc[3][c]
                      + sc[4][c] + sc[5][c] + sc[6][c] + sc[7][c];
            atomicAdd(&outR[c], sum);
        }
        // ---- grid barrier ----
        __threadfence();
        __syncthreads();
        if (tid == 0) {
            atomicAdd(&g_bar, 1u);
            unsigned tgt = (unsigned)(it + 1) * NC;
            while (atomicAdd(&g_bar, 0u) < tgt) __nanosleep(128);
        }
        __syncthreads();
        __threadfence();
    }

    // ---- phase 2: loss (S from R0, alpha from R2) ----
    float S = blocksum512(g_R0, sred);
    float al[16];
    const float* rp = g_R2 + lane * 16;
#pragma unroll
    for (int j = 0; j < 16; j++) al[j] = S / (512.0f * rp[j]);

    float lacc = 0.0f;
    for (int base = blockIdx.x * 64; base < BB; base += (int)gridDim.x * 64) {
        int row0 = base + wid * 8;
#pragma unroll
        for (int r = 0; r < 8; r++) {
            int row = row0 + r;
            const uint4* pe = (const uint4*)(g_E + (size_t)row * KK + lane * 16);
            const uint4* ps = (const uint4*)(g_Ss + (size_t)row * KK + lane * 16);
            uint4 ue0 = pe[0], ue1 = pe[1], us0 = ps[0], us1 = ps[1];
            float ev[16], v[16];
            {
                __nv_bfloat162* he0 = (__nv_bfloat162*)&ue0;
                __nv_bfloat162* he1 = (__nv_bfloat162*)&ue1;
                __nv_bfloat162* hs0 = (__nv_bfloat162*)&us0;
                __nv_bfloat162* hs1 = (__nv_bfloat162*)&us1;
#pragma unroll
                for (int k = 0; k < 4; k++) {
                    float2 f0 = __bfloat1622float2(he0[k]);
                    float2 f1 = __bfloat1622float2(he1[k]);
                    ev[k * 2] = f0.x; ev[k * 2 + 1] = f0.y;
                    ev[8 + k * 2] = f1.x; ev[8 + k * 2 + 1] = f1.y;
                    float2 g0 = __bfloat1622float2(hs0[k]);
                    float2 g1 = __bfloat1622float2(hs1[k]);
                    v[k * 2] = g0.x * INV_T; v[k * 2 + 1] = g0.y * INV_T;
                    v[8 + k * 2] = g1.x * INV_T; v[8 + k * 2 + 1] = g1.y * INV_T;
                }
            }
            float mx = v[0];
#pragma unroll
            for (int j = 1; j < 16; j++) mx = fmaxf(mx, v[j]);
#pragma unroll
            for (int o = 16; o > 0; o >>= 1)
                mx = fmaxf(mx, __shfl_xor_sync(0xffffffffu, mx, o));
            float se = 0.0f, C = 0.0f, Acc = 0.0f;
#pragma unroll
            for (int j = 0; j < 16; j++) {
                se += fexp(v[j] - mx);
                float q = ev[j] * al[j];
                C += q;
                Acc = fmaf(q, v[j], Acc);
            }
#pragma unroll
            for (int o = 16; o > 0; o >>= 1) {
                se += __shfl_xor_sync(0xffffffffu, se, o);
                C += __shfl_xor_sync(0xffffffffu, C, o);
                Acc += __shfl_xor_sync(0xffffffffu, Acc, o);
            }
            float lse = mx + logf(se);
            lacc += -(Acc - lse * C) / C;   // all lanes hold identical row sums
        }
    }
    // NOTE: every lane of the warp holds the SAME lacc (row terms were fully
    // warp-reduced) — write lane 0 only, NO further lane reduction.
    __syncthreads();
    if (lane == 0) sred[wid] = lacc;
    __syncthreads();
    if (tid == 0) {
        float b = sred[0] + sred[1] + sred[2] + sred[3]
                + sred[4] + sred[5] + sred[6] + sred[7];
        atomicAdd(&g_loss, b);
    }
}

__global__ void k_final(float* __restrict__ out) {
    out[0] = g_loss * (1.0f / 32768.0f);
}

// ---------------- launch ---------------------------------------------------------------
#define GEMM_SMEM (STAGES * STAGE_BYTES)

extern "C" void kernel_launch(void* const* d_in, const int* in_sizes, int n_in,
                              void* d_out, int out_size) {
    const float* s = nullptr;
    const float* t = nullptr;
    const float* W_net = nullptr;
    const float* W_proto = nullptr;
    for (int i = 0; i < n_in; i++) {
        long long sz = in_sizes[i];
        if (sz == (long long)BB * DD) {
            if (!s) s = (const float*)d_in[i];
            else if (!t) t = (const float*)d_in[i];
        } else if (sz == (long long)KK * DD) {
            W_net = (const float*)d_in[i];
        } else if (sz == (long long)KK * KK) {
            W_proto = (const float*)d_in[i];
        }
    }
    float* out = (float*)d_out;

    __nv_bfloat16 *Ss, *E, *Zb, *W, *Cn;
    cudaGetSymbolAddress((void**)&Ss, g_Ss);
    cudaGetSymbolAddress((void**)&E, g_E);
    cudaGetSymbolAddress((void**)&Zb, g_Zb);
    cudaGetSymbolAddress((void**)&W, g_W);
    cudaGetSymbolAddress((void**)&Cn, g_Cn);

    cudaFuncSetAttribute(k_gemm1f, cudaFuncAttributeMaxDynamicSharedMemorySize, G1_SMEM);
    cudaFuncSetAttribute(k_gemm, cudaFuncAttributeMaxDynamicSharedMemorySize, GEMM_SMEM);

    dim3 gg(KK / 128, 2 * BB / 128);   // (4, 512) batched

    // setup: proto normalize + W conv + zero init (one launch)
    k_setup<<<1024, 256>>>(W_proto, W_net);

    // batched: Zb = [s;t]@W^T (+ row sumsq); scores/E (invn inline, colsums->R0)
    k_gemm1f<<<gg, 256, G1_SMEM>>>(s, t, W, Zb);
    k_gemm<<<gg, 256, GEMM_SMEM>>>(Zb, Cn, Ss, E);

    // persistent sinkhorn (2 iterations) + loss, grid-barrier synchronized
    k_sink<<<SINK_GRID, 256>>>();
    k_final<<<1, 1>>>(out);
}